// round 15
// baseline (speedup 1.0000x reference)
#include <cuda_runtime.h>
#include <cuda_fp16.h>
#include <cstdint>

#define SQ 2048
#define DH 128
#define NH 8
#define NB 4
#define BH (NB*NH)   // 32

// fp16 operands
__device__ __half g_Qh[(size_t)BH * SQ * DH];        // scale 128^-0.25 * log2(e)
__device__ __half g_Kh[(size_t)BH * SQ * DH];        // scale 128^-0.25
__device__ __half g_Vh[(size_t)BH * SQ * DH];
__device__ __half g_Oh[(size_t)NB * SQ * NH * DH];   // attention out (fp16)
__device__ __half g_Xh[(size_t)NB * SQ * DH];        // input x (fp16)
__device__ __half g_Wth[(size_t)3 * 1024 * 128];     // QKV W^T, n-major, hi
__device__ __half g_Wtl[(size_t)3 * 1024 * 128];     // residual
__device__ __half g_Woth[(size_t)128 * 1024];        // Wo^T hi
__device__ __half g_Wotl[(size_t)128 * 1024];        // residual

// ===========================================================================
// Helpers
// ===========================================================================
__device__ __forceinline__ uint32_t smem_u32(const void* p) {
    uint32_t a;
    asm("{ .reg .u64 t; cvta.to.shared.u64 t, %1; cvt.u32.u64 %0, t; }" : "=r"(a) : "l"(p));
    return a;
}
__device__ __forceinline__ void ldsm_x4(uint32_t* r, uint32_t addr) {
    asm volatile("ldmatrix.sync.aligned.m8n8.x4.shared.b16 {%0,%1,%2,%3}, [%4];"
        : "=r"(r[0]), "=r"(r[1]), "=r"(r[2]), "=r"(r[3]) : "r"(addr));
}
__device__ __forceinline__ void ldsm_x4t(uint32_t* r, uint32_t addr) {
    asm volatile("ldmatrix.sync.aligned.m8n8.x4.trans.shared.b16 {%0,%1,%2,%3}, [%4];"
        : "=r"(r[0]), "=r"(r[1]), "=r"(r[2]), "=r"(r[3]) : "r"(addr));
}
__device__ __forceinline__ void mma16816(float* c, const uint32_t* a, const uint32_t* b) {
    asm volatile("mma.sync.aligned.m16n8k16.row.col.f32.f16.f16.f32 "
        "{%0,%1,%2,%3}, {%4,%5,%6,%7}, {%8,%9}, {%0,%1,%2,%3};"
        : "+f"(c[0]), "+f"(c[1]), "+f"(c[2]), "+f"(c[3])
        : "r"(a[0]), "r"(a[1]), "r"(a[2]), "r"(a[3]), "r"(b[0]), "r"(b[1]));
}
#define CP_ASYNC16(dst, src) \
    asm volatile("cp.async.cg.shared.global [%0], [%1], 16;" :: "r"(dst), "l"(src) : "memory")
#define CP_COMMIT() asm volatile("cp.async.commit_group;" ::: "memory")
#define CP_WAIT1()  asm volatile("cp.async.wait_group 1;" ::: "memory")
#define CP_WAIT0()  asm volatile("cp.async.wait_group 0;" ::: "memory")

// ===========================================================================
// Kernel 0: split weights (hi/lo) + x (hi only).
// ===========================================================================
__global__ __launch_bounds__(256) void split_w_kernel(
    const float* __restrict__ Wq, const float* __restrict__ Wk,
    const float* __restrict__ Wv, const float* __restrict__ Wo,
    const float* __restrict__ x)
{
    int idx = blockIdx.x * 256 + threadIdx.x;
    if (idx < 3 * 1024 * 128) {
        int k = idx & 127, n = idx >> 7;
        int mat = n >> 10, nn = n & 1023;
        const float* W = (mat == 0) ? Wq : (mat == 1) ? Wk : Wv;
        float v = W[(size_t)k * 1024 + nn];
        __half h = __float2half_rn(v);
        g_Wth[idx] = h;
        g_Wtl[idx] = __float2half_rn(v - __half2float(h));
    } else if (idx < 524288) {
        int j = idx - 393216;
        int k = j & 1023, n = j >> 10;
        float v = Wo[(size_t)k * 128 + n];
        __half h = __float2half_rn(v);
        g_Woth[j] = h;
        g_Wotl[j] = __float2half_rn(v - __half2float(h));
    } else {
        int j = idx - 524288;
        g_Xh[j] = __float2half_rn(x[j]);
    }
}

// ===========================================================================
// Kernel 1: QKV projection v3 (R12 config — col-tile 64, double-buffered
//   k-chunks of 64; this was the fastest proj variant).
// ===========================================================================
#define PJW_H   16384
#define PJW_L   24576
#define PJ_STG  32768
#define PJ_SMEM (2 * PJ_STG)   // 65536

__device__ __forceinline__ void pj_prefetch(
    uint32_t stb, const char* xh, const char* wh, const char* wl, int kc, int tid)
{
    const size_t koff = (size_t)kc * 128;
    #pragma unroll
    for (int t = 0; t < 4; t++) {               // X: 128 rows x 8 chunks
        int i = tid + t * 256;
        int r = i >> 3, j = i & 7;
        uint32_t d = (uint32_t)(r * 128 + ((j ^ (r & 7)) << 4));
        CP_ASYNC16(stb + d, xh + (size_t)r * 256 + koff + j * 16);
    }
    #pragma unroll
    for (int t = 0; t < 2; t++) {               // W: 64 rows x 8 chunks, hi+lo
        int i = tid + t * 256;
        int r = i >> 3, j = i & 7;
        uint32_t d = (uint32_t)(r * 128 + ((j ^ (r & 7)) << 4));
        size_t s = (size_t)r * 256 + koff + j * 16;
        CP_ASYNC16(stb + PJW_H + d, wh + s);
        CP_ASYNC16(stb + PJW_L + d, wl + s);
    }
}

__global__ __launch_bounds__(256, 2) void proj_kernel()
{
    extern __shared__ char smem[];
    const uint32_t sb = smem_u32(smem);
    const int tid = threadIdx.x;
    const int lane = tid & 31, warp = tid >> 5;
    const int rowBase = blockIdx.x * 128;
    const int colBase = blockIdx.y * 64;
    const int mat = colBase >> 10, wcol = colBase & 1023;

    const char* xh = (const char*)(g_Xh + (size_t)rowBase * 128);
    const char* wh = (const char*)(g_Wth + (size_t)colBase * 128);
    const char* wl = (const char*)(g_Wtl + (size_t)colBase * 128);

    pj_prefetch(sb,          xh, wh, wl, 0, tid); CP_COMMIT();
    pj_prefetch(sb + PJ_STG, xh, wh, wl, 1, tid); CP_COMMIT();

    const int lane7 = lane & 7;
    const int l34 = (lane >> 3) & 1, l4 = (lane >> 4) & 1;
    const uint32_t arow = (uint32_t)(warp * 16 + lane7 + l34 * 8);

    float sacc[8][4];
    #pragma unroll
    for (int n = 0; n < 8; n++)
        #pragma unroll
        for (int j = 0; j < 4; j++) sacc[n][j] = 0.f;

    #pragma unroll
    for (int kc = 0; kc < 2; kc++) {
        if (kc == 0) CP_WAIT1(); else CP_WAIT0();
        __syncthreads();
        const uint32_t stb = sb + (uint32_t)kc * PJ_STG;
        #pragma unroll
        for (int ks = 0; ks < 4; ks++) {
            uint32_t ah[4];
            ldsm_x4(ah, stb + arow * 128 + (uint32_t)(((2 * ks + l4) ^ lane7) << 4));
            #pragma unroll
            for (int n2 = 0; n2 < 4; n2++) {
                uint32_t wrow = (uint32_t)(n2 * 16 + lane7 + l4 * 8);
                uint32_t wchunk = (uint32_t)(((2 * ks + l34) ^ lane7) << 4);
                uint32_t bh[4], bl[4];
                ldsm_x4(bh, stb + PJW_H + wrow * 128 + wchunk);
                ldsm_x4(bl, stb + PJW_L + wrow * 128 + wchunk);
                mma16816(sacc[2*n2],   ah, bh);
                mma16816(sacc[2*n2],   ah, bl);
                mma16816(sacc[2*n2+1], ah, bh + 2);
                mma16816(sacc[2*n2+1], ah, bl + 2);
            }
        }
    }

    // 128^-0.25 = 0.29730177875068026 ; Q folds log2(e)
    const float scale = (mat == 0) ? 0.42888194248035344f
                     : (mat == 1) ? 0.29730177875068026f : 1.0f;
    __half* __restrict__ dst = (mat == 0) ? g_Qh : (mat == 1) ? g_Kh : g_Vh;
    const int r0 = rowBase + warp * 16 + (lane >> 2);
    #pragma unroll
    for (int n = 0; n < 8; n++) {
        int col = wcol + n * 8 + (lane & 3) * 2;
        int h = col >> 7, d0 = col & 127;
        #pragma unroll
        for (int half = 0; half < 2; half++) {
            int r = r0 + half * 8;
            int b = r >> 11, s = r & 2047;
            size_t idx = ((size_t)(b * NH + h) * SQ + s) * DH + d0;
            __half2 hh = __floats2half2_rn(sacc[n][half*2] * scale,
                                           sacc[n][half*2+1] * scale);
            *(uint32_t*)&dst[idx] = *(uint32_t*)&hh;
        }
    }
}

// ===========================================================================
// Kernel 2: flash attention v9 — v7 QK (8 independent chains) + softmax
//   software-pipelined against PV: exp+pack for chunk kc+1 is scheduled
//   inside chunk kc's PV MMA block (no dependency -> MUFU hides under HMMA).
// ===========================================================================
#define FA_Q      32768
#define FA_STG    32768
#define FA_VH_OFF 16384
#define FA_SMEM   (FA_Q + 2 * FA_STG)   // 98304

__device__ __forceinline__ void kv_prefetch(
    uint32_t stbase, const char* kh, const char* vh, int jt, int tid)
{
    const size_t off = (size_t)jt * 64 * 256;
    #pragma unroll
    for (int t = 0; t < 4; t++) {
        int i = tid + t * 256;
        int r = i >> 4, j = i & 15;
        uint32_t d = (uint32_t)(r * 256 + ((j ^ (r & 7)) << 4));
        size_t s = off + (size_t)r * 256 + j * 16;
        CP_ASYNC16(stbase + d,             kh + s);
        CP_ASYNC16(stbase + FA_VH_OFF + d, vh + s);
    }
}

__global__ __launch_bounds__(256, 2) void fa_kernel()
{
    extern __shared__ char smem[];
    const uint32_t sb = smem_u32(smem);
    const int tid = threadIdx.x;
    const int lane = tid & 31, warp = tid >> 5;
    const int qt = blockIdx.x, bhid = blockIdx.y;

    const size_t bh_base = (size_t)bhid * SQ * DH;
    const char* srcKh = (const char*)(g_Kh + bh_base);
    const char* srcVh = (const char*)(g_Vh + bh_base);

    {
        const char* Qh = (const char*)(g_Qh + bh_base + (size_t)qt * 128 * DH);
        #pragma unroll
        for (int t = 0; t < 8; t++) {
            int i = tid + t * 256;
            int r = i >> 4, j = i & 15;
            uint32_t d = (uint32_t)(r * 256 + ((j ^ (r & 7)) << 4));
            CP_ASYNC16(sb + d, Qh + (size_t)r * 256 + j * 16);
        }
        CP_COMMIT();
    }
    kv_prefetch(sb + FA_Q,          srcKh, srcVh, 0, tid); CP_COMMIT();
    kv_prefetch(sb + FA_Q + FA_STG, srcKh, srcVh, 1, tid); CP_COMMIT();

    const int lane7 = lane & 7;
    const int l34 = (lane >> 3) & 1, l4 = (lane >> 4) & 1;
    const int lx = lane7;
    const uint32_t qrb = sb + (uint32_t)(warp * 16 + lane7 + l34 * 8) * 256;
    const uint32_t kr0 = (uint32_t)(lane7 + l4 * 8) * 256;
    const uint32_t vr0 = FA_VH_OFF + (uint32_t)(lane7 + l34 * 8) * 256;

    float oacc[16][4];
    #pragma unroll
    for (int i = 0; i < 16; i++)
        #pragma unroll
        for (int j = 0; j < 4; j++) oacc[i][j] = 0.f;
    float rs0 = 0.f, rs1 = 0.f;

    // exp+pack one 32-key chunk c (sacc[2c], sacc[2c+1]) into dst[4]
    #define EXPCHUNK(c, dst) do {                                         \
        float p0 = exp2f(sacc[2*(c)][0]),   p1 = exp2f(sacc[2*(c)][1]);   \
        float p2 = exp2f(sacc[2*(c)][2]),   p3 = exp2f(sacc[2*(c)][3]);   \
        float u0 = exp2f(sacc[2*(c)+1][0]), u1 = exp2f(sacc[2*(c)+1][1]); \
        float u2 = exp2f(sacc[2*(c)+1][2]), u3 = exp2f(sacc[2*(c)+1][3]); \
        rs0 += (p0 + p1) + (u0 + u1);                                     \
        rs1 += (p2 + p3) + (u2 + u3);                                     \
        __half2 a01 = __floats2half2_rn(p0, p1);                          \
        __half2 a23 = __floats2half2_rn(p2, p3);                          \
        __half2 b01 = __floats2half2_rn(u0, u1);                          \
        __half2 b23 = __floats2half2_rn(u2, u3);                          \
        (dst)[0] = *(uint32_t*)&a01; (dst)[1] = *(uint32_t*)&a23;         \
        (dst)[2] = *(uint32_t*)&b01; (dst)[3] = *(uint32_t*)&b23;         \
    } while (0)

    for (int jt = 0; jt < 32; jt++) {
        if (jt < 31) CP_WAIT1(); else CP_WAIT0();
        __syncthreads();
        const uint32_t st = sb + FA_Q + (uint32_t)(jt & 1) * FA_STG;

        // ---- QK: 8 independent accumulator chains (max ILP) ----
        float sacc[8][4];
        #pragma unroll
        for (int n = 0; n < 8; n++)
            #pragma unroll
            for (int j = 0; j < 4; j++) sacc[n][j] = 0.f;

        #pragma unroll
        for (int ks = 0; ks < 8; ks++) {
            uint32_t qf[4];
            ldsm_x4(qf, qrb + (uint32_t)(((l4 + 2 * ks) ^ lx) << 4));
            uint32_t kchunk = (uint32_t)(((l34 + 2 * ks) ^ lx) << 4);
            #pragma unroll
            for (int n2 = 0; n2 < 4; n2++) {
                uint32_t bh4[4];
                ldsm_x4(bh4, st + kr0 + (uint32_t)(n2 * 4096) + kchunk);
                mma16816(sacc[2*n2],   qf, bh4);
                mma16816(sacc[2*n2+1], qf, bh4 + 2);
            }
        }

        // ---- softmax pipelined against PV ----
        uint32_t pcur[4], pnxt[4];
        EXPCHUNK(0, pcur);
        #pragma unroll
        for (int kc = 0; kc < 4; kc++) {
            if (kc < 3) EXPCHUNK(kc + 1, pnxt);   // hides under this chunk's HMMAs
            uint32_t vbase = st + vr0 + (uint32_t)(kc * 4096);
            #pragma unroll
            for (int nd2 = 0; nd2 < 8; nd2++) {
                uint32_t vf[4];
                ldsm_x4t(vf, vbase + (uint32_t)(((l4 + 2 * nd2) ^ lx) << 4));
                mma16816(oacc[2*nd2],   pcur, vf);
                mma16816(oacc[2*nd2+1], pcur, vf + 2);
            }
            if (kc < 3) {
                pcur[0] = pnxt[0]; pcur[1] = pnxt[1];
                pcur[2] = pnxt[2]; pcur[3] = pnxt[3];
            }
        }
        __syncthreads();
        if (jt + 2 < 32) {
            kv_prefetch(sb + FA_Q + (uint32_t)(jt & 1) * FA_STG,
                        srcKh, srcVh, jt + 2, tid);
            CP_COMMIT();
        }
    }
    #undef EXPCHUNK

    rs0 += __shfl_xor_sync(0xffffffffu, rs0, 1);
    rs0 += __shfl_xor_sync(0xffffffffu, rs0, 2);
    rs1 += __shfl_xor_sync(0xffffffffu, rs1, 1);
    rs1 += __shfl_xor_sync(0xffffffffu, rs1, 2);
    const float inv0 = 1.f / rs0, inv1 = 1.f / rs1;

    const int b = bhid >> 3, h = bhid & 7;
    const int r0 = warp * 16 + (lane >> 2);
    const size_t row = (size_t)b * SQ + qt * 128 + r0;
    const size_t idx0 = row * (NH * DH) + h * DH + (lane & 3) * 2;
    const size_t idx1 = idx0 + (size_t)8 * (NH * DH);
    #pragma unroll
    for (int nd = 0; nd < 16; nd++) {
        __half2 h0 = __floats2half2_rn(oacc[nd][0] * inv0, oacc[nd][1] * inv0);
        __half2 h1 = __floats2half2_rn(oacc[nd][2] * inv1, oacc[nd][3] * inv1);
        *(uint32_t*)&g_Oh[idx0 + nd * 8] = *(uint32_t*)&h0;
        *(uint32_t*)&g_Oh[idx1 + nd * 8] = *(uint32_t*)&h1;
    }
}

// ===========================================================================
// Kernel 3: output projection v4 (unchanged from R12).
// ===========================================================================
#define OPS_BH  16384
#define OPS_BL  32768
#define OP_STG  49152
#define OP_SMEM (2 * OP_STG)   // 98304

__device__ __forceinline__ void op_prefetch(
    uint32_t stb, const char* Ah, const char* Bh, const char* Bl, int kc, int tid)
{
    const size_t koff = (size_t)kc * 256;
    #pragma unroll
    for (int t = 0; t < 4; t++) {
        int i = tid + t * 256;
        int r = i >> 4, j = i & 15;
        uint32_t d = (uint32_t)(r * 256 + ((j ^ (r & 7)) << 4));
        size_t s = (size_t)r * 2048 + koff + j * 16;
        CP_ASYNC16(stb + d,          Ah + s);
        CP_ASYNC16(stb + OPS_BH + d, Bh + s);
        CP_ASYNC16(stb + OPS_BL + d, Bl + s);
    }
}

__global__ __launch_bounds__(256, 2) void outproj_kernel(
    const float* __restrict__ bo, float* __restrict__ out)
{
    extern __shared__ char smem[];
    const uint32_t sb = smem_u32(smem);
    const int tid = threadIdx.x;
    const int lane = tid & 31, warp = tid >> 5;
    const int ms = warp >> 1, nhf = warp & 1;
    const int rowBase = blockIdx.x * 64;
    const int colBase = blockIdx.y * 64;

    const char* Ah = (const char*)(g_Oh + (size_t)rowBase * 1024);
    const char* Bh = (const char*)(g_Woth + (size_t)colBase * 1024);
    const char* Bl = (const char*)(g_Wotl + (size_t)colBase * 1024);

    const int lane7 = lane & 7;
    const int l34 = (lane >> 3) & 1, l4 = (lane >> 4) & 1;
    const uint32_t arow = (uint32_t)(ms * 16 + l34 * 8 + lane7);
    const uint32_t brow = (uint32_t)(nhf * 32 + lane7 + l4 * 8);

    op_prefetch(sb, Ah, Bh, Bl, 0, tid);
    CP_COMMIT();

    float sacc[4][4];
    #pragma unroll
    for (int n = 0; n < 4; n++)
        #pragma unroll
        for (int j = 0; j < 4; j++) sacc[n][j] = 0.f;

    for (int kc = 0; kc < 8; kc++) {
        if (kc + 1 < 8) {
            op_prefetch(sb + (uint32_t)((kc + 1) & 1) * OP_STG, Ah, Bh, Bl, kc + 1, tid);
            CP_COMMIT();
            CP_WAIT1();
        } else {
            CP_WAIT0();
        }
        __syncthreads();

        const uint32_t stb = sb + (uint32_t)(kc & 1) * OP_STG;
        #pragma unroll
        for (int ks = 0; ks < 8; ks++) {
            uint32_t ah[4];
            ldsm_x4(ah, stb + arow * 256 + (uint32_t)(((2 * ks + l4) ^ lane7) << 4));
            uint32_t bchunk = (uint32_t)(((2 * ks + l34) ^ lane7) << 4);
            #pragma unroll
            for (int n2 = 0; n2 < 2; n2++) {
                uint32_t brow2 = brow + (uint32_t)(n2 * 16);
                uint32_t bh[4], bl[4];
                ldsm_x4(bh, stb + OPS_BH + brow2 * 256 + bchunk);
                ldsm_x4(bl, stb + OPS_BL + brow2 * 256 + bchunk);
                mma16816(sacc[2*n2],   ah, bh);
                mma16816(sacc[2*n2],   ah, bl);
                mma16816(sacc[2*n2+1], ah, bh + 2);
                mma16816(sacc[2*n2+1], ah, bl + 2);
            }
        }
        __syncthreads();
    }

    const int r0 = rowBase + ms * 16 + (lane >> 2);
    #pragma unroll
    for (int n = 0; n < 4; n++) {
        int col = colBase + nhf * 32 + n * 8 + (lane & 3) * 2;
        float b0 = bo[col], b1 = bo[col + 1];
        *(float2*)&out[(size_t)r0 * 128 + col] =
            make_float2(sacc[n][0] + b0, sacc[n][1] + b1);
        *(float2*)&out[(size_t)(r0 + 8) * 128 + col] =
            make_float2(sacc[n][2] + b0, sacc[n][3] + b1);
    }
}

// ===========================================================================
extern "C" void kernel_launch(void* const* d_in, const int* in_sizes, int n_in,
                              void* d_out, int out_size)
{
    const float* x  = (const float*)d_in[0];
    const float* Wq = (const float*)d_in[1];
    const float* Wk = (const float*)d_in[2];
    const float* Wv = (const float*)d_in[3];
    const float* Wo = (const float*)d_in[4];
    const float* bo = (const float*)d_in[5];
    float* out = (float*)d_out;

    cudaFuncSetAttribute(proj_kernel,
                         cudaFuncAttributeMaxDynamicSharedMemorySize, PJ_SMEM);
    cudaFuncSetAttribute(fa_kernel,
                         cudaFuncAttributeMaxDynamicSharedMemorySize, FA_SMEM);
    cudaFuncSetAttribute(outproj_kernel,
                         cudaFuncAttributeMaxDynamicSharedMemorySize, OP_SMEM);

    split_w_kernel<<<6144, 256>>>(Wq, Wk, Wv, Wo, x);
    proj_kernel<<<dim3(64, 48), 256, PJ_SMEM>>>();
    fa_kernel<<<dim3(16, 32), 256, FA_SMEM>>>();
    outproj_kernel<<<dim3(128, 2), 256, OP_SMEM>>>(bo, out);
}

// round 16
// speedup vs baseline: 1.0088x; 1.0088x over previous
#include <cuda_runtime.h>
#include <cuda_fp16.h>
#include <cstdint>

#define SQ 2048
#define DH 128
#define NH 8
#define NB 4
#define BH (NB*NH)   // 32

// fp16 operands
__device__ __half g_Qh[(size_t)BH * SQ * DH];        // scale 128^-0.25 * log2(e)
__device__ __half g_Kh[(size_t)BH * SQ * DH];        // scale 128^-0.25
__device__ __half g_Vh[(size_t)BH * SQ * DH];
__device__ __half g_Oh[(size_t)NB * SQ * NH * DH];   // attention out (fp16)
__device__ __half g_Xh[(size_t)NB * SQ * DH];        // input x (fp16)
__device__ __half g_Wth[(size_t)3 * 1024 * 128];     // QKV W^T, n-major, hi
__device__ __half g_Wtl[(size_t)3 * 1024 * 128];     // residual
__device__ __half g_Woth[(size_t)128 * 1024];        // Wo^T hi
__device__ __half g_Wotl[(size_t)128 * 1024];        // residual

// ===========================================================================
// Helpers
// ===========================================================================
__device__ __forceinline__ uint32_t smem_u32(const void* p) {
    uint32_t a;
    asm("{ .reg .u64 t; cvta.to.shared.u64 t, %1; cvt.u32.u64 %0, t; }" : "=r"(a) : "l"(p));
    return a;
}
__device__ __forceinline__ void ldsm_x4(uint32_t* r, uint32_t addr) {
    asm volatile("ldmatrix.sync.aligned.m8n8.x4.shared.b16 {%0,%1,%2,%3}, [%4];"
        : "=r"(r[0]), "=r"(r[1]), "=r"(r[2]), "=r"(r[3]) : "r"(addr));
}
__device__ __forceinline__ void ldsm_x4t(uint32_t* r, uint32_t addr) {
    asm volatile("ldmatrix.sync.aligned.m8n8.x4.trans.shared.b16 {%0,%1,%2,%3}, [%4];"
        : "=r"(r[0]), "=r"(r[1]), "=r"(r[2]), "=r"(r[3]) : "r"(addr));
}
__device__ __forceinline__ void mma16816(float* c, const uint32_t* a, const uint32_t* b) {
    asm volatile("mma.sync.aligned.m16n8k16.row.col.f32.f16.f16.f32 "
        "{%0,%1,%2,%3}, {%4,%5,%6,%7}, {%8,%9}, {%0,%1,%2,%3};"
        : "+f"(c[0]), "+f"(c[1]), "+f"(c[2]), "+f"(c[3])
        : "r"(a[0]), "r"(a[1]), "r"(a[2]), "r"(a[3]), "r"(b[0]), "r"(b[1]));
}
#define CP_ASYNC16(dst, src) \
    asm volatile("cp.async.cg.shared.global [%0], [%1], 16;" :: "r"(dst), "l"(src) : "memory")
#define CP_COMMIT() asm volatile("cp.async.commit_group;" ::: "memory")
#define CP_WAIT0()  asm volatile("cp.async.wait_group 0;" ::: "memory")

// ===========================================================================
// Kernel 0: split weights (hi/lo) + x (hi only).
// ===========================================================================
__global__ __launch_bounds__(256) void split_w_kernel(
    const float* __restrict__ Wq, const float* __restrict__ Wk,
    const float* __restrict__ Wv, const float* __restrict__ Wo,
    const float* __restrict__ x)
{
    int idx = blockIdx.x * 256 + threadIdx.x;
    if (idx < 3 * 1024 * 128) {
        int k = idx & 127, n = idx >> 7;
        int mat = n >> 10, nn = n & 1023;
        const float* W = (mat == 0) ? Wq : (mat == 1) ? Wk : Wv;
        float v = W[(size_t)k * 1024 + nn];
        __half h = __float2half_rn(v);
        g_Wth[idx] = h;
        g_Wtl[idx] = __float2half_rn(v - __half2float(h));
    } else if (idx < 524288) {
        int j = idx - 393216;
        int k = j & 1023, n = j >> 10;
        float v = Wo[(size_t)k * 128 + n];
        __half h = __float2half_rn(v);
        g_Woth[j] = h;
        g_Wotl[j] = __float2half_rn(v - __half2float(h));
    } else {
        int j = idx - 524288;
        g_Xh[j] = __float2half_rn(x[j]);
    }
}

// ===========================================================================
// Kernel 1: QKV projection v3 (R12 config) with single-sync 1-ahead pipeline.
// ===========================================================================
#define PJW_H   16384
#define PJW_L   24576
#define PJ_STG  32768
#define PJ_SMEM (2 * PJ_STG)   // 65536

__device__ __forceinline__ void pj_prefetch(
    uint32_t stb, const char* xh, const char* wh, const char* wl, int kc, int tid)
{
    const size_t koff = (size_t)kc * 128;
    #pragma unroll
    for (int t = 0; t < 4; t++) {               // X: 128 rows x 8 chunks
        int i = tid + t * 256;
        int r = i >> 3, j = i & 7;
        uint32_t d = (uint32_t)(r * 128 + ((j ^ (r & 7)) << 4));
        CP_ASYNC16(stb + d, xh + (size_t)r * 256 + koff + j * 16);
    }
    #pragma unroll
    for (int t = 0; t < 2; t++) {               // W: 64 rows x 8 chunks, hi+lo
        int i = tid + t * 256;
        int r = i >> 3, j = i & 7;
        uint32_t d = (uint32_t)(r * 128 + ((j ^ (r & 7)) << 4));
        size_t s = (size_t)r * 256 + koff + j * 16;
        CP_ASYNC16(stb + PJW_H + d, wh + s);
        CP_ASYNC16(stb + PJW_L + d, wl + s);
    }
}

__global__ __launch_bounds__(256, 2) void proj_kernel()
{
    extern __shared__ char smem[];
    const uint32_t sb = smem_u32(smem);
    const int tid = threadIdx.x;
    const int lane = tid & 31, warp = tid >> 5;
    const int rowBase = blockIdx.x * 128;
    const int colBase = blockIdx.y * 64;
    const int mat = colBase >> 10, wcol = colBase & 1023;

    const char* xh = (const char*)(g_Xh + (size_t)rowBase * 128);
    const char* wh = (const char*)(g_Wth + (size_t)colBase * 128);
    const char* wl = (const char*)(g_Wtl + (size_t)colBase * 128);

    pj_prefetch(sb, xh, wh, wl, 0, tid); CP_COMMIT();

    const int lane7 = lane & 7;
    const int l34 = (lane >> 3) & 1, l4 = (lane >> 4) & 1;
    const uint32_t arow = (uint32_t)(warp * 16 + lane7 + l34 * 8);

    float sacc[8][4];
    #pragma unroll
    for (int n = 0; n < 8; n++)
        #pragma unroll
        for (int j = 0; j < 4; j++) sacc[n][j] = 0.f;

    #pragma unroll
    for (int kc = 0; kc < 2; kc++) {
        CP_WAIT0();
        __syncthreads();
        if (kc == 0) { pj_prefetch(sb + PJ_STG, xh, wh, wl, 1, tid); CP_COMMIT(); }
        const uint32_t stb = sb + (uint32_t)kc * PJ_STG;
        #pragma unroll
        for (int ks = 0; ks < 4; ks++) {
            uint32_t ah[4];
            ldsm_x4(ah, stb + arow * 128 + (uint32_t)(((2 * ks + l4) ^ lane7) << 4));
            #pragma unroll
            for (int n2 = 0; n2 < 4; n2++) {
                uint32_t wrow = (uint32_t)(n2 * 16 + lane7 + l4 * 8);
                uint32_t wchunk = (uint32_t)(((2 * ks + l34) ^ lane7) << 4);
                uint32_t bh[4], bl[4];
                ldsm_x4(bh, stb + PJW_H + wrow * 128 + wchunk);
                ldsm_x4(bl, stb + PJW_L + wrow * 128 + wchunk);
                mma16816(sacc[2*n2],   ah, bh);
                mma16816(sacc[2*n2],   ah, bl);
                mma16816(sacc[2*n2+1], ah, bh + 2);
                mma16816(sacc[2*n2+1], ah, bl + 2);
            }
        }
    }

    // 128^-0.25 = 0.29730177875068026 ; Q folds log2(e)
    const float scale = (mat == 0) ? 0.42888194248035344f
                     : (mat == 1) ? 0.29730177875068026f : 1.0f;
    __half* __restrict__ dst = (mat == 0) ? g_Qh : (mat == 1) ? g_Kh : g_Vh;
    const int r0 = rowBase + warp * 16 + (lane >> 2);
    #pragma unroll
    for (int n = 0; n < 8; n++) {
        int col = wcol + n * 8 + (lane & 3) * 2;
        int h = col >> 7, d0 = col & 127;
        #pragma unroll
        for (int half = 0; half < 2; half++) {
            int r = r0 + half * 8;
            int b = r >> 11, s = r & 2047;
            size_t idx = ((size_t)(b * NH + h) * SQ + s) * DH + d0;
            __half2 hh = __floats2half2_rn(sacc[n][half*2] * scale,
                                           sacc[n][half*2+1] * scale);
            *(uint32_t*)&dst[idx] = *(uint32_t*)&hh;
        }
    }
}

// ===========================================================================
// Kernel 2: flash attention v7 with single-sync 1-ahead KV pipeline.
//   (QK 8 independent chains; exp2 block; PV; ONE barrier per tile.)
// ===========================================================================
#define FA_Q      32768
#define FA_STG    32768
#define FA_VH_OFF 16384
#define FA_SMEM   (FA_Q + 2 * FA_STG)   // 98304

__device__ __forceinline__ void kv_prefetch(
    uint32_t stbase, const char* kh, const char* vh, int jt, int tid)
{
    const size_t off = (size_t)jt * 64 * 256;
    #pragma unroll
    for (int t = 0; t < 4; t++) {
        int i = tid + t * 256;
        int r = i >> 4, j = i & 15;
        uint32_t d = (uint32_t)(r * 256 + ((j ^ (r & 7)) << 4));
        size_t s = off + (size_t)r * 256 + j * 16;
        CP_ASYNC16(stbase + d,             kh + s);
        CP_ASYNC16(stbase + FA_VH_OFF + d, vh + s);
    }
}

__global__ __launch_bounds__(256, 2) void fa_kernel()
{
    extern __shared__ char smem[];
    const uint32_t sb = smem_u32(smem);
    const int tid = threadIdx.x;
    const int lane = tid & 31, warp = tid >> 5;
    const int qt = blockIdx.x, bhid = blockIdx.y;

    const size_t bh_base = (size_t)bhid * SQ * DH;
    const char* srcKh = (const char*)(g_Kh + bh_base);
    const char* srcVh = (const char*)(g_Vh + bh_base);

    // Q tile + stage-0 KV (one group; WAIT0 at jt=0 covers both)
    {
        const char* Qh = (const char*)(g_Qh + bh_base + (size_t)qt * 128 * DH);
        #pragma unroll
        for (int t = 0; t < 8; t++) {
            int i = tid + t * 256;
            int r = i >> 4, j = i & 15;
            uint32_t d = (uint32_t)(r * 256 + ((j ^ (r & 7)) << 4));
            CP_ASYNC16(sb + d, Qh + (size_t)r * 256 + j * 16);
        }
    }
    kv_prefetch(sb + FA_Q, srcKh, srcVh, 0, tid);
    CP_COMMIT();

    const int lane7 = lane & 7;
    const int l34 = (lane >> 3) & 1, l4 = (lane >> 4) & 1;
    const int lx = lane7;
    const uint32_t qrb = sb + (uint32_t)(warp * 16 + lane7 + l34 * 8) * 256;
    const uint32_t kr0 = (uint32_t)(lane7 + l4 * 8) * 256;
    const uint32_t vr0 = FA_VH_OFF + (uint32_t)(lane7 + l34 * 8) * 256;

    float oacc[16][4];
    #pragma unroll
    for (int i = 0; i < 16; i++)
        #pragma unroll
        for (int j = 0; j < 4; j++) oacc[i][j] = 0.f;
    float rs0 = 0.f, rs1 = 0.f;

    for (int jt = 0; jt < 32; jt++) {
        CP_WAIT0();            // stage jt&1 (the only outstanding group) complete
        __syncthreads();       // doubles as: all warps done reading stage (jt+1)&1
        if (jt + 1 < 32) {
            kv_prefetch(sb + FA_Q + (uint32_t)((jt + 1) & 1) * FA_STG,
                        srcKh, srcVh, jt + 1, tid);
            CP_COMMIT();
        }
        const uint32_t st = sb + FA_Q + (uint32_t)(jt & 1) * FA_STG;

        // ---- QK: 8 independent accumulator chains ----
        float sacc[8][4];
        #pragma unroll
        for (int n = 0; n < 8; n++)
            #pragma unroll
            for (int j = 0; j < 4; j++) sacc[n][j] = 0.f;

        #pragma unroll
        for (int ks = 0; ks < 8; ks++) {
            uint32_t qf[4];
            ldsm_x4(qf, qrb + (uint32_t)(((l4 + 2 * ks) ^ lx) << 4));
            uint32_t kchunk = (uint32_t)(((l34 + 2 * ks) ^ lx) << 4);
            #pragma unroll
            for (int n2 = 0; n2 < 4; n2++) {
                uint32_t bh4[4];
                ldsm_x4(bh4, st + kr0 + (uint32_t)(n2 * 4096) + kchunk);
                mma16816(sacc[2*n2],   qf, bh4);
                mma16816(sacc[2*n2+1], qf, bh4 + 2);
            }
        }

        // ---- p = exp2(s); fp32 denom; pack fp16 ----
        uint32_t pa[8][2];
        #pragma unroll
        for (int n = 0; n < 8; n++) {
            float p0 = exp2f(sacc[n][0]);
            float p1 = exp2f(sacc[n][1]);
            float p2 = exp2f(sacc[n][2]);
            float p3 = exp2f(sacc[n][3]);
            rs0 += p0 + p1;
            rs1 += p2 + p3;
            __half2 q01 = __floats2half2_rn(p0, p1);
            __half2 q23 = __floats2half2_rn(p2, p3);
            pa[n][0] = *(uint32_t*)&q01;
            pa[n][1] = *(uint32_t*)&q23;
        }

        // ---- O += P Vh ----
        #pragma unroll
        for (int kc = 0; kc < 4; kc++) {
            uint32_t pah[4] = { pa[2*kc][0], pa[2*kc][1], pa[2*kc+1][0], pa[2*kc+1][1] };
            uint32_t vbase = st + vr0 + (uint32_t)(kc * 4096);
            #pragma unroll
            for (int nd2 = 0; nd2 < 8; nd2++) {
                uint32_t vf[4];
                ldsm_x4t(vf, vbase + (uint32_t)(((l4 + 2 * nd2) ^ lx) << 4));
                mma16816(oacc[2*nd2],   pah, vf);
                mma16816(oacc[2*nd2+1], pah, vf + 2);
            }
        }
    }

    rs0 += __shfl_xor_sync(0xffffffffu, rs0, 1);
    rs0 += __shfl_xor_sync(0xffffffffu, rs0, 2);
    rs1 += __shfl_xor_sync(0xffffffffu, rs1, 1);
    rs1 += __shfl_xor_sync(0xffffffffu, rs1, 2);
    const float inv0 = 1.f / rs0, inv1 = 1.f / rs1;

    const int b = bhid >> 3, h = bhid & 7;
    const int r0 = warp * 16 + (lane >> 2);
    const size_t row = (size_t)b * SQ + qt * 128 + r0;
    const size_t idx0 = row * (NH * DH) + h * DH + (lane & 3) * 2;
    const size_t idx1 = idx0 + (size_t)8 * (NH * DH);
    #pragma unroll
    for (int nd = 0; nd < 16; nd++) {
        __half2 h0 = __floats2half2_rn(oacc[nd][0] * inv0, oacc[nd][1] * inv0);
        __half2 h1 = __floats2half2_rn(oacc[nd][2] * inv1, oacc[nd][3] * inv1);
        *(uint32_t*)&g_Oh[idx0 + nd * 8] = *(uint32_t*)&h0;
        *(uint32_t*)&g_Oh[idx1 + nd * 8] = *(uint32_t*)&h1;
    }
}

// ===========================================================================
// Kernel 3: output projection v4 with single-sync 1-ahead pipeline.
// ===========================================================================
#define OPS_BH  16384
#define OPS_BL  32768
#define OP_STG  49152
#define OP_SMEM (2 * OP_STG)   // 98304

__device__ __forceinline__ void op_prefetch(
    uint32_t stb, const char* Ah, const char* Bh, const char* Bl, int kc, int tid)
{
    const size_t koff = (size_t)kc * 256;
    #pragma unroll
    for (int t = 0; t < 4; t++) {
        int i = tid + t * 256;
        int r = i >> 4, j = i & 15;
        uint32_t d = (uint32_t)(r * 256 + ((j ^ (r & 7)) << 4));
        size_t s = (size_t)r * 2048 + koff + j * 16;
        CP_ASYNC16(stb + d,          Ah + s);
        CP_ASYNC16(stb + OPS_BH + d, Bh + s);
        CP_ASYNC16(stb + OPS_BL + d, Bl + s);
    }
}

__global__ __launch_bounds__(256, 2) void outproj_kernel(
    const float* __restrict__ bo, float* __restrict__ out)
{
    extern __shared__ char smem[];
    const uint32_t sb = smem_u32(smem);
    const int tid = threadIdx.x;
    const int lane = tid & 31, warp = tid >> 5;
    const int ms = warp >> 1, nhf = warp & 1;
    const int rowBase = blockIdx.x * 64;
    const int colBase = blockIdx.y * 64;

    const char* Ah = (const char*)(g_Oh + (size_t)rowBase * 1024);
    const char* Bh = (const char*)(g_Woth + (size_t)colBase * 1024);
    const char* Bl = (const char*)(g_Wotl + (size_t)colBase * 1024);

    const int lane7 = lane & 7;
    const int l34 = (lane >> 3) & 1, l4 = (lane >> 4) & 1;
    const uint32_t arow = (uint32_t)(ms * 16 + l34 * 8 + lane7);
    const uint32_t brow = (uint32_t)(nhf * 32 + lane7 + l4 * 8);

    op_prefetch(sb, Ah, Bh, Bl, 0, tid);
    CP_COMMIT();

    float sacc[4][4];
    #pragma unroll
    for (int n = 0; n < 4; n++)
        #pragma unroll
        for (int j = 0; j < 4; j++) sacc[n][j] = 0.f;

    for (int kc = 0; kc < 8; kc++) {
        CP_WAIT0();
        __syncthreads();
        if (kc + 1 < 8) {
            op_prefetch(sb + (uint32_t)((kc + 1) & 1) * OP_STG, Ah, Bh, Bl, kc + 1, tid);
            CP_COMMIT();
        }
        const uint32_t stb = sb + (uint32_t)(kc & 1) * OP_STG;
        #pragma unroll
        for (int ks = 0; ks < 8; ks++) {
            uint32_t ah[4];
            ldsm_x4(ah, stb + arow * 256 + (uint32_t)(((2 * ks + l4) ^ lane7) << 4));
            uint32_t bchunk = (uint32_t)(((2 * ks + l34) ^ lane7) << 4);
            #pragma unroll
            for (int n2 = 0; n2 < 2; n2++) {
                uint32_t brow2 = brow + (uint32_t)(n2 * 16);
                uint32_t bh[4], bl[4];
                ldsm_x4(bh, stb + OPS_BH + brow2 * 256 + bchunk);
                ldsm_x4(bl, stb + OPS_BL + brow2 * 256 + bchunk);
                mma16816(sacc[2*n2],   ah, bh);
                mma16816(sacc[2*n2],   ah, bl);
                mma16816(sacc[2*n2+1], ah, bh + 2);
                mma16816(sacc[2*n2+1], ah, bl + 2);
            }
        }
    }

    const int r0 = rowBase + ms * 16 + (lane >> 2);
    #pragma unroll
    for (int n = 0; n < 4; n++) {
        int col = colBase + nhf * 32 + n * 8 + (lane & 3) * 2;
        float b0 = bo[col], b1 = bo[col + 1];
        *(float2*)&out[(size_t)r0 * 128 + col] =
            make_float2(sacc[n][0] + b0, sacc[n][1] + b1);
        *(float2*)&out[(size_t)(r0 + 8) * 128 + col] =
            make_float2(sacc[n][2] + b0, sacc[n][3] + b1);
    }
}

// ===========================================================================
extern "C" void kernel_launch(void* const* d_in, const int* in_sizes, int n_in,
                              void* d_out, int out_size)
{
    const float* x  = (const float*)d_in[0];
    const float* Wq = (const float*)d_in[1];
    const float* Wk = (const float*)d_in[2];
    const float* Wv = (const float*)d_in[3];
    const float* Wo = (const float*)d_in[4];
    const float* bo = (const float*)d_in[5];
    float* out = (float*)d_out;

    cudaFuncSetAttribute(proj_kernel,
                         cudaFuncAttributeMaxDynamicSharedMemorySize, PJ_SMEM);
    cudaFuncSetAttribute(fa_kernel,
                         cudaFuncAttributeMaxDynamicSharedMemorySize, FA_SMEM);
    cudaFuncSetAttribute(outproj_kernel,
                         cudaFuncAttributeMaxDynamicSharedMemorySize, OP_SMEM);

    split_w_kernel<<<6144, 256>>>(Wq, Wk, Wv, Wo, x);
    proj_kernel<<<dim3(64, 48), 256, PJ_SMEM>>>();
    fa_kernel<<<dim3(16, 32), 256, FA_SMEM>>>();
    outproj_kernel<<<dim3(128, 2), 256, OP_SMEM>>>(bo, out);
}

// round 17
// speedup vs baseline: 1.0461x; 1.0370x over previous
#include <cuda_runtime.h>
#include <cuda_fp16.h>
#include <cstdint>

#define SQ 2048
#define DH 128
#define NH 8
#define NB 4
#define BH (NB*NH)   // 32

// fp16 operands
__device__ __half g_Qh[(size_t)BH * SQ * DH];        // scale 128^-0.25 * log2(e)
__device__ __half g_Kh[(size_t)BH * SQ * DH];        // scale 128^-0.25
__device__ __half g_Vh[(size_t)BH * SQ * DH];
__device__ __half g_Oh[(size_t)NB * SQ * NH * DH];   // attention out (fp16)
__device__ __half g_Xh[(size_t)NB * SQ * DH];        // input x (fp16)
__device__ __half g_Wth[(size_t)3 * 1024 * 128];     // QKV W^T, n-major, hi
__device__ __half g_Wtl[(size_t)3 * 1024 * 128];     // residual
__device__ __half g_Woth[(size_t)128 * 1024];        // Wo^T hi (lo dropped)

// ===========================================================================
// Helpers
// ===========================================================================
__device__ __forceinline__ uint32_t smem_u32(const void* p) {
    uint32_t a;
    asm("{ .reg .u64 t; cvta.to.shared.u64 t, %1; cvt.u32.u64 %0, t; }" : "=r"(a) : "l"(p));
    return a;
}
__device__ __forceinline__ void ldsm_x4(uint32_t* r, uint32_t addr) {
    asm volatile("ldmatrix.sync.aligned.m8n8.x4.shared.b16 {%0,%1,%2,%3}, [%4];"
        : "=r"(r[0]), "=r"(r[1]), "=r"(r[2]), "=r"(r[3]) : "r"(addr));
}
__device__ __forceinline__ void ldsm_x4t(uint32_t* r, uint32_t addr) {
    asm volatile("ldmatrix.sync.aligned.m8n8.x4.trans.shared.b16 {%0,%1,%2,%3}, [%4];"
        : "=r"(r[0]), "=r"(r[1]), "=r"(r[2]), "=r"(r[3]) : "r"(addr));
}
__device__ __forceinline__ void mma16816(float* c, const uint32_t* a, const uint32_t* b) {
    asm volatile("mma.sync.aligned.m16n8k16.row.col.f32.f16.f16.f32 "
        "{%0,%1,%2,%3}, {%4,%5,%6,%7}, {%8,%9}, {%0,%1,%2,%3};"
        : "+f"(c[0]), "+f"(c[1]), "+f"(c[2]), "+f"(c[3])
        : "r"(a[0]), "r"(a[1]), "r"(a[2]), "r"(a[3]), "r"(b[0]), "r"(b[1]));
}
#define CP_ASYNC16(dst, src) \
    asm volatile("cp.async.cg.shared.global [%0], [%1], 16;" :: "r"(dst), "l"(src) : "memory")
#define CP_COMMIT() asm volatile("cp.async.commit_group;" ::: "memory")
#define CP_WAIT1()  asm volatile("cp.async.wait_group 1;" ::: "memory")
#define CP_WAIT0()  asm volatile("cp.async.wait_group 0;" ::: "memory")

// ===========================================================================
// Kernel 0: split/transpose via smem tiles (coalesced both directions).
//   blocks [0,384): QKV W (128k x 3072n) -> Wth/Wtl [n][k]
//   blocks [384,512): Wo (1024k x 128n)  -> Woth [n][k] (hi only)
//   blocks [512,1024): x fp32 -> fp16 (vectorized straight copy)
// ===========================================================================
__global__ __launch_bounds__(256) void split_w_kernel(
    const float* __restrict__ Wq, const float* __restrict__ Wk,
    const float* __restrict__ Wv, const float* __restrict__ Wo,
    const float* __restrict__ x)
{
    __shared__ float s[32][33];
    const int blk = blockIdx.x;
    const int tid = threadIdx.x;
    const int tx = tid & 31, ty = tid >> 5;

    if (blk < 384) {
        const int kt = blk & 3, nt = blk >> 2;        // k-tile [0,4), n-tile [0,96)
        const int mat = (nt * 32) >> 10;
        const int nn0 = (nt * 32) & 1023;
        const float* __restrict__ W = (mat == 0) ? Wq : (mat == 1) ? Wk : Wv;
        #pragma unroll
        for (int i = 0; i < 4; i++)
            s[ty + i * 8][tx] = W[(size_t)(kt * 32 + ty + i * 8) * 1024 + nn0 + tx];
        __syncthreads();
        #pragma unroll
        for (int i = 0; i < 4; i++) {
            int n = nt * 32 + ty + i * 8;
            int k = kt * 32 + tx;
            float v = s[tx][ty + i * 8];
            __half h = __float2half_rn(v);
            size_t idx = (size_t)n * 128 + k;
            g_Wth[idx] = h;
            g_Wtl[idx] = __float2half_rn(v - __half2float(h));
        }
    } else if (blk < 512) {
        const int b2 = blk - 384;
        const int kt = b2 & 31, nt = b2 >> 5;         // k-tile [0,32), n-tile [0,4)
        #pragma unroll
        for (int i = 0; i < 4; i++)
            s[ty + i * 8][tx] = Wo[(size_t)(kt * 32 + ty + i * 8) * 128 + nt * 32 + tx];
        __syncthreads();
        #pragma unroll
        for (int i = 0; i < 4; i++) {
            int n = nt * 32 + ty + i * 8;
            int k = kt * 32 + tx;
            g_Woth[(size_t)n * 1024 + k] = __float2half_rn(s[tx][ty + i * 8]);
        }
    } else {
        const int b3 = blk - 512;                     // [0,512): 2048 elems each
        const size_t base = (size_t)b3 * 2048 + tid * 4;
        #pragma unroll
        for (int p = 0; p < 2; p++) {
            size_t off = base + (size_t)p * 1024;
            float4 v = *(const float4*)&x[off];
            __half2 h0 = __floats2half2_rn(v.x, v.y);
            __half2 h1 = __floats2half2_rn(v.z, v.w);
            *(uint2*)&g_Xh[off] = make_uint2(*(uint32_t*)&h0, *(uint32_t*)&h1);
        }
    }
}

// ===========================================================================
// Kernel 1: QKV projection v3 (R12 exact — col-tile 64, double-buffered
//   k-chunks of 64, WAIT1 pipeline).
// ===========================================================================
#define PJW_H   16384
#define PJW_L   24576
#define PJ_STG  32768
#define PJ_SMEM (2 * PJ_STG)   // 65536

__device__ __forceinline__ void pj_prefetch(
    uint32_t stb, const char* xh, const char* wh, const char* wl, int kc, int tid)
{
    const size_t koff = (size_t)kc * 128;
    #pragma unroll
    for (int t = 0; t < 4; t++) {               // X: 128 rows x 8 chunks
        int i = tid + t * 256;
        int r = i >> 3, j = i & 7;
        uint32_t d = (uint32_t)(r * 128 + ((j ^ (r & 7)) << 4));
        CP_ASYNC16(stb + d, xh + (size_t)r * 256 + koff + j * 16);
    }
    #pragma unroll
    for (int t = 0; t < 2; t++) {               // W: 64 rows x 8 chunks, hi+lo
        int i = tid + t * 256;
        int r = i >> 3, j = i & 7;
        uint32_t d = (uint32_t)(r * 128 + ((j ^ (r & 7)) << 4));
        size_t s = (size_t)r * 256 + koff + j * 16;
        CP_ASYNC16(stb + PJW_H + d, wh + s);
        CP_ASYNC16(stb + PJW_L + d, wl + s);
    }
}

__global__ __launch_bounds__(256, 2) void proj_kernel()
{
    extern __shared__ char smem[];
    const uint32_t sb = smem_u32(smem);
    const int tid = threadIdx.x;
    const int lane = tid & 31, warp = tid >> 5;
    const int rowBase = blockIdx.x * 128;
    const int colBase = blockIdx.y * 64;
    const int mat = colBase >> 10, wcol = colBase & 1023;

    const char* xh = (const char*)(g_Xh + (size_t)rowBase * 128);
    const char* wh = (const char*)(g_Wth + (size_t)colBase * 128);
    const char* wl = (const char*)(g_Wtl + (size_t)colBase * 128);

    pj_prefetch(sb,          xh, wh, wl, 0, tid); CP_COMMIT();
    pj_prefetch(sb + PJ_STG, xh, wh, wl, 1, tid); CP_COMMIT();

    const int lane7 = lane & 7;
    const int l34 = (lane >> 3) & 1, l4 = (lane >> 4) & 1;
    const uint32_t arow = (uint32_t)(warp * 16 + lane7 + l34 * 8);

    float sacc[8][4];
    #pragma unroll
    for (int n = 0; n < 8; n++)
        #pragma unroll
        for (int j = 0; j < 4; j++) sacc[n][j] = 0.f;

    #pragma unroll
    for (int kc = 0; kc < 2; kc++) {
        if (kc == 0) CP_WAIT1(); else CP_WAIT0();
        __syncthreads();
        const uint32_t stb = sb + (uint32_t)kc * PJ_STG;
        #pragma unroll
        for (int ks = 0; ks < 4; ks++) {
            uint32_t ah[4];
            ldsm_x4(ah, stb + arow * 128 + (uint32_t)(((2 * ks + l4) ^ lane7) << 4));
            #pragma unroll
            for (int n2 = 0; n2 < 4; n2++) {
                uint32_t wrow = (uint32_t)(n2 * 16 + lane7 + l4 * 8);
                uint32_t wchunk = (uint32_t)(((2 * ks + l34) ^ lane7) << 4);
                uint32_t bh[4], bl[4];
                ldsm_x4(bh, stb + PJW_H + wrow * 128 + wchunk);
                ldsm_x4(bl, stb + PJW_L + wrow * 128 + wchunk);
                mma16816(sacc[2*n2],   ah, bh);
                mma16816(sacc[2*n2],   ah, bl);
                mma16816(sacc[2*n2+1], ah, bh + 2);
                mma16816(sacc[2*n2+1], ah, bl + 2);
            }
        }
    }

    // 128^-0.25 = 0.29730177875068026 ; Q folds log2(e)
    const float scale = (mat == 0) ? 0.42888194248035344f
                     : (mat == 1) ? 0.29730177875068026f : 1.0f;
    __half* __restrict__ dst = (mat == 0) ? g_Qh : (mat == 1) ? g_Kh : g_Vh;
    const int r0 = rowBase + warp * 16 + (lane >> 2);
    #pragma unroll
    for (int n = 0; n < 8; n++) {
        int col = wcol + n * 8 + (lane & 3) * 2;
        int h = col >> 7, d0 = col & 127;
        #pragma unroll
        for (int half = 0; half < 2; half++) {
            int r = r0 + half * 8;
            int b = r >> 11, s = r & 2047;
            size_t idx = ((size_t)(b * NH + h) * SQ + s) * DH + d0;
            __half2 hh = __floats2half2_rn(sacc[n][half*2] * scale,
                                           sacc[n][half*2+1] * scale);
            *(uint32_t*)&dst[idx] = *(uint32_t*)&hh;
        }
    }
}

// ===========================================================================
// Kernel 2: flash attention v7 (R12 exact).
// ===========================================================================
#define FA_Q      32768
#define FA_STG    32768
#define FA_VH_OFF 16384
#define FA_SMEM   (FA_Q + 2 * FA_STG)   // 98304

__device__ __forceinline__ void kv_prefetch(
    uint32_t stbase, const char* kh, const char* vh, int jt, int tid)
{
    const size_t off = (size_t)jt * 64 * 256;
    #pragma unroll
    for (int t = 0; t < 4; t++) {
        int i = tid + t * 256;
        int r = i >> 4, j = i & 15;
        uint32_t d = (uint32_t)(r * 256 + ((j ^ (r & 7)) << 4));
        size_t s = off + (size_t)r * 256 + j * 16;
        CP_ASYNC16(stbase + d,             kh + s);
        CP_ASYNC16(stbase + FA_VH_OFF + d, vh + s);
    }
}

__global__ __launch_bounds__(256, 2) void fa_kernel()
{
    extern __shared__ char smem[];
    const uint32_t sb = smem_u32(smem);
    const int tid = threadIdx.x;
    const int lane = tid & 31, warp = tid >> 5;
    const int qt = blockIdx.x, bhid = blockIdx.y;

    const size_t bh_base = (size_t)bhid * SQ * DH;
    const char* srcKh = (const char*)(g_Kh + bh_base);
    const char* srcVh = (const char*)(g_Vh + bh_base);

    {
        const char* Qh = (const char*)(g_Qh + bh_base + (size_t)qt * 128 * DH);
        #pragma unroll
        for (int t = 0; t < 8; t++) {
            int i = tid + t * 256;
            int r = i >> 4, j = i & 15;
            uint32_t d = (uint32_t)(r * 256 + ((j ^ (r & 7)) << 4));
            CP_ASYNC16(sb + d, Qh + (size_t)r * 256 + j * 16);
        }
        CP_COMMIT();
    }
    kv_prefetch(sb + FA_Q,          srcKh, srcVh, 0, tid); CP_COMMIT();
    kv_prefetch(sb + FA_Q + FA_STG, srcKh, srcVh, 1, tid); CP_COMMIT();

    const int lane7 = lane & 7;
    const int l34 = (lane >> 3) & 1, l4 = (lane >> 4) & 1;
    const int lx = lane7;
    const uint32_t qrb = sb + (uint32_t)(warp * 16 + lane7 + l34 * 8) * 256;
    const uint32_t kr0 = (uint32_t)(lane7 + l4 * 8) * 256;
    const uint32_t vr0 = FA_VH_OFF + (uint32_t)(lane7 + l34 * 8) * 256;

    float oacc[16][4];
    #pragma unroll
    for (int i = 0; i < 16; i++)
        #pragma unroll
        for (int j = 0; j < 4; j++) oacc[i][j] = 0.f;
    float rs0 = 0.f, rs1 = 0.f;

    for (int jt = 0; jt < 32; jt++) {
        if (jt < 31) CP_WAIT1(); else CP_WAIT0();
        __syncthreads();
        const uint32_t st = sb + FA_Q + (uint32_t)(jt & 1) * FA_STG;

        float sacc[8][4];
        #pragma unroll
        for (int n = 0; n < 8; n++)
            #pragma unroll
            for (int j = 0; j < 4; j++) sacc[n][j] = 0.f;

        #pragma unroll
        for (int ks = 0; ks < 8; ks++) {
            uint32_t qf[4];
            ldsm_x4(qf, qrb + (uint32_t)(((l4 + 2 * ks) ^ lx) << 4));
            uint32_t kchunk = (uint32_t)(((l34 + 2 * ks) ^ lx) << 4);
            #pragma unroll
            for (int n2 = 0; n2 < 4; n2++) {
                uint32_t bh4[4];
                ldsm_x4(bh4, st + kr0 + (uint32_t)(n2 * 4096) + kchunk);
                mma16816(sacc[2*n2],   qf, bh4);
                mma16816(sacc[2*n2+1], qf, bh4 + 2);
            }
        }

        uint32_t pa[8][2];
        #pragma unroll
        for (int n = 0; n < 8; n++) {
            float p0 = exp2f(sacc[n][0]);
            float p1 = exp2f(sacc[n][1]);
            float p2 = exp2f(sacc[n][2]);
            float p3 = exp2f(sacc[n][3]);
            rs0 += p0 + p1;
            rs1 += p2 + p3;
            __half2 q01 = __floats2half2_rn(p0, p1);
            __half2 q23 = __floats2half2_rn(p2, p3);
            pa[n][0] = *(uint32_t*)&q01;
            pa[n][1] = *(uint32_t*)&q23;
        }

        #pragma unroll
        for (int kc = 0; kc < 4; kc++) {
            uint32_t pah[4] = { pa[2*kc][0], pa[2*kc][1], pa[2*kc+1][0], pa[2*kc+1][1] };
            uint32_t vbase = st + vr0 + (uint32_t)(kc * 4096);
            #pragma unroll
            for (int nd2 = 0; nd2 < 8; nd2++) {
                uint32_t vf[4];
                ldsm_x4t(vf, vbase + (uint32_t)(((l4 + 2 * nd2) ^ lx) << 4));
                mma16816(oacc[2*nd2],   pah, vf);
                mma16816(oacc[2*nd2+1], pah, vf + 2);
            }
        }
        __syncthreads();
        if (jt + 2 < 32) {
            kv_prefetch(sb + FA_Q + (uint32_t)(jt & 1) * FA_STG,
                        srcKh, srcVh, jt + 2, tid);
            CP_COMMIT();
        }
    }

    rs0 += __shfl_xor_sync(0xffffffffu, rs0, 1);
    rs0 += __shfl_xor_sync(0xffffffffu, rs0, 2);
    rs1 += __shfl_xor_sync(0xffffffffu, rs1, 1);
    rs1 += __shfl_xor_sync(0xffffffffu, rs1, 2);
    const float inv0 = 1.f / rs0, inv1 = 1.f / rs1;

    const int b = bhid >> 3, h = bhid & 7;
    const int r0 = warp * 16 + (lane >> 2);
    const size_t row = (size_t)b * SQ + qt * 128 + r0;
    const size_t idx0 = row * (NH * DH) + h * DH + (lane & 3) * 2;
    const size_t idx1 = idx0 + (size_t)8 * (NH * DH);
    #pragma unroll
    for (int nd = 0; nd < 16; nd++) {
        __half2 h0 = __floats2half2_rn(oacc[nd][0] * inv0, oacc[nd][1] * inv0);
        __half2 h1 = __floats2half2_rn(oacc[nd][2] * inv1, oacc[nd][3] * inv1);
        *(uint32_t*)&g_Oh[idx0 + nd * 8] = *(uint32_t*)&h0;
        *(uint32_t*)&g_Oh[idx1 + nd * 8] = *(uint32_t*)&h1;
    }
}

// ===========================================================================
// Kernel 3: output projection v5 — Wo hi only (1 product), double-buffered
//   k-chunks of 128. grid (128 row-tiles of 64, 2 col-tiles of 64).
// ===========================================================================
#define OPS_BH  16384
#define OP_STG  32768
#define OP_SMEM (2 * OP_STG)   // 65536

__device__ __forceinline__ void op_prefetch(
    uint32_t stb, const char* Ah, const char* Bh, int kc, int tid)
{
    const size_t koff = (size_t)kc * 256;
    #pragma unroll
    for (int t = 0; t < 4; t++) {
        int i = tid + t * 256;
        int r = i >> 4, j = i & 15;
        uint32_t d = (uint32_t)(r * 256 + ((j ^ (r & 7)) << 4));
        size_t s = (size_t)r * 2048 + koff + j * 16;
        CP_ASYNC16(stb + d,          Ah + s);
        CP_ASYNC16(stb + OPS_BH + d, Bh + s);
    }
}

__global__ __launch_bounds__(256, 2) void outproj_kernel(
    const float* __restrict__ bo, float* __restrict__ out)
{
    extern __shared__ char smem[];
    const uint32_t sb = smem_u32(smem);
    const int tid = threadIdx.x;
    const int lane = tid & 31, warp = tid >> 5;
    const int ms = warp >> 1, nhf = warp & 1;
    const int rowBase = blockIdx.x * 64;
    const int colBase = blockIdx.y * 64;

    const char* Ah = (const char*)(g_Oh + (size_t)rowBase * 1024);
    const char* Bh = (const char*)(g_Woth + (size_t)colBase * 1024);

    const int lane7 = lane & 7;
    const int l34 = (lane >> 3) & 1, l4 = (lane >> 4) & 1;
    const uint32_t arow = (uint32_t)(ms * 16 + l34 * 8 + lane7);
    const uint32_t brow = (uint32_t)(nhf * 32 + lane7 + l4 * 8);

    op_prefetch(sb, Ah, Bh, 0, tid);
    CP_COMMIT();

    float sacc[4][4];
    #pragma unroll
    for (int n = 0; n < 4; n++)
        #pragma unroll
        for (int j = 0; j < 4; j++) sacc[n][j] = 0.f;

    for (int kc = 0; kc < 8; kc++) {
        if (kc + 1 < 8) {
            op_prefetch(sb + (uint32_t)((kc + 1) & 1) * OP_STG, Ah, Bh, kc + 1, tid);
            CP_COMMIT();
            CP_WAIT1();
        } else {
            CP_WAIT0();
        }
        __syncthreads();

        const uint32_t stb = sb + (uint32_t)(kc & 1) * OP_STG;
        #pragma unroll
        for (int ks = 0; ks < 8; ks++) {
            uint32_t ah[4];
            ldsm_x4(ah, stb + arow * 256 + (uint32_t)(((2 * ks + l4) ^ lane7) << 4));
            uint32_t bchunk = (uint32_t)(((2 * ks + l34) ^ lane7) << 4);
            #pragma unroll
            for (int n2 = 0; n2 < 2; n2++) {
                uint32_t brow2 = brow + (uint32_t)(n2 * 16);
                uint32_t bh[4];
                ldsm_x4(bh, stb + OPS_BH + brow2 * 256 + bchunk);
                mma16816(sacc[2*n2],   ah, bh);
                mma16816(sacc[2*n2+1], ah, bh + 2);
            }
        }
        __syncthreads();
    }

    const int r0 = rowBase + ms * 16 + (lane >> 2);
    #pragma unroll
    for (int n = 0; n < 4; n++) {
        int col = colBase + nhf * 32 + n * 8 + (lane & 3) * 2;
        float b0 = bo[col], b1 = bo[col + 1];
        *(float2*)&out[(size_t)r0 * 128 + col] =
            make_float2(sacc[n][0] + b0, sacc[n][1] + b1);
        *(float2*)&out[(size_t)(r0 + 8) * 128 + col] =
            make_float2(sacc[n][2] + b0, sacc[n][3] + b1);
    }
}

// ===========================================================================
extern "C" void kernel_launch(void* const* d_in, const int* in_sizes, int n_in,
                              void* d_out, int out_size)
{
    const float* x  = (const float*)d_in[0];
    const float* Wq = (const float*)d_in[1];
    const float* Wk = (const float*)d_in[2];
    const float* Wv = (const float*)d_in[3];
    const float* Wo = (const float*)d_in[4];
    const float* bo = (const float*)d_in[5];
    float* out = (float*)d_out;

    cudaFuncSetAttribute(proj_kernel,
                         cudaFuncAttributeMaxDynamicSharedMemorySize, PJ_SMEM);
    cudaFuncSetAttribute(fa_kernel,
                         cudaFuncAttributeMaxDynamicSharedMemorySize, FA_SMEM);
    cudaFuncSetAttribute(outproj_kernel,
                         cudaFuncAttributeMaxDynamicSharedMemorySize, OP_SMEM);

    split_w_kernel<<<1024, 256>>>(Wq, Wk, Wv, Wo, x);
    proj_kernel<<<dim3(64, 48), 256, PJ_SMEM>>>();
    fa_kernel<<<dim3(16, 32), 256, FA_SMEM>>>();
    outproj_kernel<<<dim3(128, 2), 256, OP_SMEM>>>(bo, out);
}